// round 2
// baseline (speedup 1.0000x reference)
#include <cuda_runtime.h>

#define Bsz 8
#define Cch 64
#define Hh  128
#define Wwi 128
#define Och 64
#define HW  (Hh*Wwi)

#define TILE_ROWS 4
#define THREADS   512

// smem layout (floats):
//  Wt padded: [c=64][k=9][og=4][18]  (16 used + 2 pad for bank-skew) = 41472
//  gs tile:   [k=9][rl=4][128]                                        = 4608
//  x tile:    [6][132]                                                = 792
#define WT_PAD_SZ (64*9*4*18)
#define GS_SZ     (9*TILE_ROWS*128)
#define XS_SZ     (6*132)
#define SMEM_FLOATS (WT_PAD_SZ + GS_SZ + XS_SZ)

__device__ float d_wt[Cch*9*Och];   // transposed weight: [c][k][o]

extern __shared__ float smem[];

__device__ __forceinline__ float tanh_fast(float v) {
    float y;
    asm("tanh.approx.f32 %0, %1;" : "=f"(y) : "f"(v));
    return y;
}

__device__ __forceinline__ unsigned long long pack2(float a) {
    unsigned long long r;
    asm("mov.b64 %0, {%1, %1};" : "=l"(r) : "f"(a));
    return r;
}

__device__ __forceinline__ void ffma2(unsigned long long &acc,
                                      unsigned long long a,
                                      unsigned long long w) {
    asm("fma.rn.f32x2 %0, %1, %2, %0;" : "+l"(acc) : "l"(a), "l"(w));
}

__device__ __forceinline__ float2 unpack2(unsigned long long v) {
    float2 r;
    asm("mov.b64 {%0, %1}, %2;" : "=f"(r.x), "=f"(r.y) : "l"(v));
    return r;
}

// One-time weight transpose: w[o][c][k] (o*576 + c*9 + k) -> d_wt[c][k][o]
__global__ void paka_transpose_w(const float* __restrict__ w) {
    int idx = blockIdx.x * blockDim.x + threadIdx.x;
    if (idx < Cch*9*Och) {
        int o  = idx & 63;
        int ck = idx >> 6;                 // c*9 + k
        d_wt[idx] = w[o * (Cch*9) + ck];
    }
}

__global__ void __launch_bounds__(THREADS, 1)
paka_kernel(const float* __restrict__ x,
            const float* __restrict__ gc,
            const float* __restrict__ gsp,
            float* __restrict__ out)
{
    float* Wt  = smem;                     // WT_PAD_SZ
    float* gss = smem + WT_PAD_SZ;         // GS_SZ
    float* xs  = gss + GS_SZ;              // XS_SZ

    const int tid = threadIdx.x;
    const int b   = blockIdx.y;
    const int r0  = blockIdx.x * TILE_ROWS;

    // ---- stage weight (coalesced read from d_wt, skewed write) ----
    #pragma unroll 4
    for (int v = tid; v < Cch*9*Och; v += THREADS) {
        int o  = v & 63;
        int ck = v >> 6;                   // c*9 + k
        int dst = ck * 72 + (o >> 4) * 18 + (o & 15);
        Wt[dst] = d_wt[v];
    }
    // ---- stage gs tile ----
    for (int i = tid; i < GS_SZ; i += THREADS) {
        int col = i & 127;
        int krl = i >> 7;                  // k*4 + rl
        int k  = krl >> 2;
        int rl = krl & 3;
        gss[i] = gsp[(((size_t)b*9 + k)*Hh + (r0 + rl))*Wwi + col];
    }

    const int og   = tid & 3;              // 16-output group
    const int pg   = tid >> 2;             // 0..127 pixel group
    const int rl   = pg >> 5;              // 0..3
    const int col0 = (pg & 31) << 2;       // 0..124 step 4
    const int r    = r0 + rl;

    unsigned long long acc[4][8];
    #pragma unroll
    for (int p = 0; p < 4; ++p)
        #pragma unroll
        for (int j = 0; j < 8; ++j) acc[p][j] = 0ull;

    const float* x_base  = x  + (size_t)b*Cch*HW;
    const float* gc_base = gc + (size_t)b*Cch*HW + (size_t)r*Wwi + col0;

    for (int c = 0; c < Cch; ++c) {
        __syncthreads();   // previous iteration's xs reads complete
        // ---- stage x halo tile: rows r0-1..r0+4, cols -1..130 ----
        #pragma unroll
        for (int i = tid; i < XS_SZ; i += THREADS) {
            int row = i / 132;
            int j   = i - row * 132;
            int gh  = r0 - 1 + row;
            int gw  = j - 1;
            float v = 0.f;
            if ((unsigned)gh < Hh && (unsigned)gw < Wwi)
                v = x_base[(size_t)c*HW + gh*Wwi + gw];
            xs[i] = v;
        }
        const float4 gcv = *(const float4*)(gc_base + (size_t)c*HW);
        __syncthreads();

        const float* wck = Wt + c * (9*72) + og * 18;

        #pragma unroll
        for (int di = 0; di < 3; ++di) {
            const float* xr = xs + (rl + di) * 132 + col0;
            const float4 xv4 = *(const float4*)xr;
            const float2 xv2 = *(const float2*)(xr + 4);
            const float xrow[6] = {xv4.x, xv4.y, xv4.z, xv4.w, xv2.x, xv2.y};
            #pragma unroll
            for (int dj = 0; dj < 3; ++dj) {
                const int k = di*3 + dj;
                const float4 gsv = *(const float4*)(gss + (k*TILE_ROWS + rl)*128 + col0);
                const float t0 = tanh_fast(gcv.x + gsv.x);
                const float t1 = tanh_fast(gcv.y + gsv.y);
                const float t2 = tanh_fast(gcv.z + gsv.z);
                const float t3 = tanh_fast(gcv.w + gsv.w);
                unsigned long long ap0 = pack2(fmaf(xrow[dj+0], t0, xrow[dj+0]));
                unsigned long long ap1 = pack2(fmaf(xrow[dj+1], t1, xrow[dj+1]));
                unsigned long long ap2 = pack2(fmaf(xrow[dj+2], t2, xrow[dj+2]));
                unsigned long long ap3 = pack2(fmaf(xrow[dj+3], t3, xrow[dj+3]));
                const unsigned long long* wp =
                    (const unsigned long long*)(wck + k * 72);
                #pragma unroll
                for (int j = 0; j < 8; ++j) {
                    const unsigned long long wj = wp[j];
                    ffma2(acc[0][j], ap0, wj);
                    ffma2(acc[1][j], ap1, wj);
                    ffma2(acc[2][j], ap2, wj);
                    ffma2(acc[3][j], ap3, wj);
                }
            }
        }
    }

    // ---- store: p-vectorized float4 per output channel ----
    float* outp = out + ((size_t)b*Och*Hh + r)*Wwi + col0;
    #pragma unroll
    for (int j = 0; j < 8; ++j) {
        const float2 v0 = unpack2(acc[0][j]);
        const float2 v1 = unpack2(acc[1][j]);
        const float2 v2 = unpack2(acc[2][j]);
        const float2 v3 = unpack2(acc[3][j]);
        const int o0 = og*16 + 2*j;
        const float4 lo = make_float4(v0.x, v1.x, v2.x, v3.x);
        const float4 hi = make_float4(v0.y, v1.y, v2.y, v3.y);
        *(float4*)(outp + (size_t)o0     * HW) = lo;
        *(float4*)(outp + (size_t)(o0+1) * HW) = hi;
    }
}

extern "C" void kernel_launch(void* const* d_in, const int* in_sizes, int n_in,
                              void* d_out, int out_size) {
    const float* x  = (const float*)d_in[0];
    const float* gc = (const float*)d_in[1];
    const float* gs = (const float*)d_in[2];
    const float* w  = (const float*)d_in[3];
    float* out = (float*)d_out;

    paka_transpose_w<<<(Cch*9*Och + 1023)/1024, 1024>>>(w);

    const size_t smem_bytes = SMEM_FLOATS * sizeof(float);
    static bool attr_set = false;
    (void)cudaFuncSetAttribute(paka_kernel,
                               cudaFuncAttributeMaxDynamicSharedMemorySize,
                               (int)smem_bytes);
    (void)attr_set;

    dim3 grid(Hh / TILE_ROWS, Bsz);   // (32, 8)
    paka_kernel<<<grid, THREADS, smem_bytes>>>(x, gc, gs, out);
}

// round 3
// speedup vs baseline: 1.3895x; 1.3895x over previous
#include <cuda_runtime.h>
#include <cstdint>

#define Bsz 8
#define Cch 64
#define Hh  128
#define Wwi 128
#define Och 64
#define HW  (Hh*Wwi)

#define TILE_ROWS 4
#define THREADS   512
#define CSTEP     4
#define NGROUPS   (Cch/CSTEP)      // 16

// smem layout (floats):
//  Wt padded: [ck=576][og=4][20]  (16 used + 4 pad, 16B-aligned, bank-disjoint) = 46080
//  gs tile:   [k=9][rl=4][128]                                                  = 4608
//  x tiles:   2 buffers x [CSTEP][6][132]                                       = 6336
#define WT_STRIDE_OG 20
#define WT_STRIDE_CK (4*WT_STRIDE_OG)      // 80
#define WT_PAD_SZ (576*WT_STRIDE_CK)       // 46080
#define GS_SZ     (9*TILE_ROWS*128)        // 4608
#define XS_CH     (6*132)                  // 792
#define XS_G      (CSTEP*XS_CH)            // 3168
#define XS_SZ     (2*XS_G)                 // 6336
#define SMEM_FLOATS (WT_PAD_SZ + GS_SZ + XS_SZ)   // 57024 fl = 228096 B

__device__ float d_wt[Cch*9*Och];   // transposed weight: [c][k][o]

extern __shared__ float smem[];

__device__ __forceinline__ float tanh_fast(float v) {
    float y;
    asm("tanh.approx.f32 %0, %1;" : "=f"(y) : "f"(v));
    return y;
}
__device__ __forceinline__ unsigned long long pack2(float a) {
    unsigned long long r;
    asm("mov.b64 %0, {%1, %1};" : "=l"(r) : "f"(a));
    return r;
}
__device__ __forceinline__ void ffma2(unsigned long long &acc,
                                      unsigned long long a,
                                      unsigned long long w) {
    asm("fma.rn.f32x2 %0, %1, %2, %0;" : "+l"(acc) : "l"(a), "l"(w));
}
__device__ __forceinline__ float2 unpack2(unsigned long long v) {
    float2 r;
    asm("mov.b64 {%0, %1}, %2;" : "=f"(r.x), "=f"(r.y) : "l"(v));
    return r;
}
__device__ __forceinline__ uint32_t smem_u32(const void* p) {
    uint32_t a;
    asm("{ .reg .u64 t; cvta.to.shared.u64 t, %1; cvt.u32.u64 %0, t; }"
        : "=r"(a) : "l"(p));
    return a;
}
__device__ __forceinline__ void cp4(uint32_t dst, const void* src, int nbytes) {
    asm volatile("cp.async.ca.shared.global [%0], [%1], 4, %2;"
                 :: "r"(dst), "l"(src), "r"(nbytes));
}
__device__ __forceinline__ void cp_commit() {
    asm volatile("cp.async.commit_group;");
}
__device__ __forceinline__ void cp_wait0() {
    asm volatile("cp.async.wait_group 0;" ::: "memory");
}

// One-time weight transpose: w[o][c][k] (o*576 + c*9 + k) -> d_wt[c][k][o]
__global__ void paka_transpose_w(const float* __restrict__ w) {
    int idx = blockIdx.x * blockDim.x + threadIdx.x;
    if (idx < Cch*9*Och) {
        int o  = idx & 63;
        int ck = idx >> 6;                 // c*9 + k
        d_wt[idx] = w[o * (Cch*9) + ck];
    }
}

// stage x channels [c0, c0+CSTEP) into xs buffer `buf` via cp.async (zero-fill halo)
__device__ __forceinline__ void stage_x_group(const float* __restrict__ x_base,
                                              uint32_t xs_u32, int buf,
                                              int c0, int r0, int tid)
{
    const float* xc = x_base + (size_t)c0 * HW;
    const uint32_t dst0 = xs_u32 + (uint32_t)buf * (XS_G*4);
    #pragma unroll
    for (int it = 0; it < (XS_G + THREADS - 1) / THREADS; ++it) {
        int idx = tid + it * THREADS;
        if (idx < XS_G) {
            int ch  = idx / XS_CH;
            int rem = idx - ch * XS_CH;
            int row = rem / 132;
            int col = rem - row * 132;
            int gh  = r0 - 1 + row;
            int gw  = col - 1;
            bool inb = ((unsigned)gh < Hh) & ((unsigned)gw < Wwi);
            const float* src = inb ? (xc + (size_t)ch*HW + gh*Wwi + gw) : x_base;
            cp4(dst0 + (uint32_t)idx*4, src, inb ? 4 : 0);
        }
    }
    cp_commit();
}

__global__ void __launch_bounds__(THREADS, 1)
paka_kernel(const float* __restrict__ x,
            const float* __restrict__ gc,
            const float* __restrict__ gsp,
            float* __restrict__ out)
{
    float* Wt  = smem;                     // WT_PAD_SZ
    float* gss = smem + WT_PAD_SZ;         // GS_SZ
    float* xs  = gss + GS_SZ;              // XS_SZ
    const uint32_t xs_u32 = smem_u32(xs);

    const int tid = threadIdx.x;
    const int b   = blockIdx.y;
    const int r0  = blockIdx.x * TILE_ROWS;

    const float* x_base = x + (size_t)b*Cch*HW;

    // ---- prefetch group 0 of x first (longest latency, overlaps staging below) ----
    stage_x_group(x_base, xs_u32, 0, 0, r0, tid);

    // ---- stage weight (coalesced read from d_wt, skewed+aligned write) ----
    #pragma unroll 4
    for (int v = tid; v < Cch*9*Och; v += THREADS) {
        int o  = v & 63;
        int ck = v >> 6;                   // c*9 + k
        int dst = ck * WT_STRIDE_CK + (o >> 4) * WT_STRIDE_OG + (o & 15);
        Wt[dst] = d_wt[v];
    }
    // ---- stage gs tile ----
    for (int i = tid; i < GS_SZ; i += THREADS) {
        int col = i & 127;
        int krl = i >> 7;                  // k*4 + rl
        int k  = krl >> 2;
        int rl = krl & 3;
        gss[i] = gsp[(((size_t)b*9 + k)*Hh + (r0 + rl))*Wwi + col];
    }

    const int og   = tid & 3;              // 16-output group
    const int pg   = tid >> 2;             // 0..127 pixel group
    const int rl   = pg >> 5;              // 0..3
    const int col0 = (pg & 31) << 2;       // 0..124 step 4
    const int r    = r0 + rl;

    unsigned long long acc[4][8];
    #pragma unroll
    for (int p = 0; p < 4; ++p)
        #pragma unroll
        for (int j = 0; j < 8; ++j) acc[p][j] = 0ull;

    const float* gc_base = gc + (size_t)b*Cch*HW + (size_t)r*Wwi + col0;

    // register prefetch of gc for channel 0
    float4 gcn = *(const float4*)(gc_base);

    for (int g = 0; g < NGROUPS; ++g) {
        const int buf = g & 1;
        cp_wait0();                 // my async copies for this buffer done
        __syncthreads();            // everyone's copies visible; prev compute done
        if (g + 1 < NGROUPS)
            stage_x_group(x_base, xs_u32, buf ^ 1, (g + 1) * CSTEP, r0, tid);

        const float* xsg = xs + buf * XS_G;

        #pragma unroll
        for (int cc = 0; cc < CSTEP; ++cc) {
            const int c = g * CSTEP + cc;
            const float4 gcv = gcn;
            {   // prefetch next channel's gc (clamped)
                int cn = c + 1; if (cn > Cch-1) cn = Cch-1;
                gcn = *(const float4*)(gc_base + (size_t)cn*HW);
            }
            const float* wck = Wt + c * (9*WT_STRIDE_CK) + og * WT_STRIDE_OG;
            const float* xch = xsg + cc * XS_CH;

            #pragma unroll
            for (int di = 0; di < 3; ++di) {
                const float* xr = xch + (rl + di) * 132 + col0;
                const float4 xv4 = *(const float4*)xr;
                const float2 xv2 = *(const float2*)(xr + 4);
                const float xrow[6] = {xv4.x, xv4.y, xv4.z, xv4.w, xv2.x, xv2.y};
                #pragma unroll
                for (int dj = 0; dj < 3; ++dj) {
                    const int k = di*3 + dj;
                    const float4 gsv = *(const float4*)(gss + (k*TILE_ROWS + rl)*128 + col0);
                    const float t0 = tanh_fast(gcv.x + gsv.x);
                    const float t1 = tanh_fast(gcv.y + gsv.y);
                    const float t2 = tanh_fast(gcv.z + gsv.z);
                    const float t3 = tanh_fast(gcv.w + gsv.w);
                    unsigned long long ap0 = pack2(fmaf(xrow[dj+0], t0, xrow[dj+0]));
                    unsigned long long ap1 = pack2(fmaf(xrow[dj+1], t1, xrow[dj+1]));
                    unsigned long long ap2 = pack2(fmaf(xrow[dj+2], t2, xrow[dj+2]));
                    unsigned long long ap3 = pack2(fmaf(xrow[dj+3], t3, xrow[dj+3]));
                    const ulonglong2* wp =
                        (const ulonglong2*)(wck + k * WT_STRIDE_CK);
                    #pragma unroll
                    for (int j2 = 0; j2 < 4; ++j2) {
                        const ulonglong2 wv = wp[j2];
                        ffma2(acc[0][2*j2+0], ap0, wv.x);
                        ffma2(acc[1][2*j2+0], ap1, wv.x);
                        ffma2(acc[2][2*j2+0], ap2, wv.x);
                        ffma2(acc[3][2*j2+0], ap3, wv.x);
                        ffma2(acc[0][2*j2+1], ap0, wv.y);
                        ffma2(acc[1][2*j2+1], ap1, wv.y);
                        ffma2(acc[2][2*j2+1], ap2, wv.y);
                        ffma2(acc[3][2*j2+1], ap3, wv.y);
                    }
                }
            }
        }
    }

    // ---- store: p-vectorized float4 per output channel ----
    float* outp = out + ((size_t)b*Och*Hh + r)*Wwi + col0;
    #pragma unroll
    for (int j = 0; j < 8; ++j) {
        const float2 v0 = unpack2(acc[0][j]);
        const float2 v1 = unpack2(acc[1][j]);
        const float2 v2 = unpack2(acc[2][j]);
        const float2 v3 = unpack2(acc[3][j]);
        const int o0 = og*16 + 2*j;
        const float4 lo = make_float4(v0.x, v1.x, v2.x, v3.x);
        const float4 hi = make_float4(v0.y, v1.y, v2.y, v3.y);
        *(float4*)(outp + (size_t)o0     * HW) = lo;
        *(float4*)(outp + (size_t)(o0+1) * HW) = hi;
    }
}

extern "C" void kernel_launch(void* const* d_in, const int* in_sizes, int n_in,
                              void* d_out, int out_size) {
    const float* x  = (const float*)d_in[0];
    const float* gc = (const float*)d_in[1];
    const float* gs = (const float*)d_in[2];
    const float* w  = (const float*)d_in[3];
    float* out = (float*)d_out;

    paka_transpose_w<<<(Cch*9*Och + 1023)/1024, 1024>>>(w);

    const size_t smem_bytes = SMEM_FLOATS * sizeof(float);
    (void)cudaFuncSetAttribute(paka_kernel,
                               cudaFuncAttributeMaxDynamicSharedMemorySize,
                               (int)smem_bytes);

    dim3 grid(Hh / TILE_ROWS, Bsz);   // (32, 8)
    paka_kernel<<<grid, THREADS, smem_bytes>>>(x, gc, gs, out);
}

// round 6
// speedup vs baseline: 2.8054x; 2.0190x over previous
#include <cuda_runtime.h>
#include <cuda_fp16.h>
#include <cstdint>

#define Bsz 8
#define Cch 64
#define Hh  128
#define Wwi 128
#define Och 64
#define HW  (Hh*Wwi)

#define THREADS 256
#define NTILES  (Bsz*Hh)        // 1024 blocks, 1 tile each
#define NSTEPS  36              // K=576 / 16
#define NCHUNK  4               // 16 channels per chunk, 9 k-steps per chunk

// smem (floats): two chunk buffers [x: 16ch x (3*132 rows, stride-padded 400) | gc: 16 x 136]
// plus gs [9 x 136]
#define XSTR    400
#define XGC_OFF 6400            // 16*400
#define GCSTR   136
#define BUF_FL  (XGC_OFF + 16*GCSTR)   // 8576
#define GS_OFF  (2*BUF_FL)             // 17152
#define GSSTR   136
#define SMEM_FL (GS_OFF + 9*GSSTR)     // 18376 -> 73504 B

#define X_ELEMS 6336            // 16*3*132
#define GC_ELEMS 2048           // 16*128
#define GS_ELEMS 1152           // 9*128

// B pre-packed HMMA fragments: [step 36][lane 32][nt 8] x uint2 {b0,b1}
__device__ uint2 d_bfrag[NSTEPS*32*8];

// ---------------- helpers ----------------
__device__ __forceinline__ uint32_t smem_u32(const void* p) {
    uint32_t a;
    asm("{ .reg .u64 t; cvta.to.shared.u64 t, %1; cvt.u32.u64 %0, t; }"
        : "=r"(a) : "l"(p));
    return a;
}
__device__ __forceinline__ float tanh_fast(float v) {
    float y; asm("tanh.approx.f32 %0, %1;" : "=f"(y) : "f"(v)); return y;
}
__device__ __forceinline__ void cp4(uint32_t dst, const void* src, int nbytes) {
    asm volatile("cp.async.ca.shared.global [%0], [%1], 4, %2;"
                 :: "r"(dst), "l"(src), "r"(nbytes));
}
__device__ __forceinline__ void cp_commit() {
    asm volatile("cp.async.commit_group;");
}
__device__ __forceinline__ void cp_wait1() {
    asm volatile("cp.async.wait_group 1;" ::: "memory");
}
__device__ __forceinline__ void cp_wait0() {
    asm volatile("cp.async.wait_group 0;" ::: "memory");
}
__device__ __forceinline__ uint32_t packh2(float lo, float hi) {
    __half2 h = __floats2half2_rn(lo, hi);
    return *reinterpret_cast<uint32_t*>(&h);
}
__device__ __forceinline__ void hmma(float& c0, float& c1, float& c2, float& c3,
                                     uint32_t a0, uint32_t a1, uint32_t a2, uint32_t a3,
                                     uint32_t b0, uint32_t b1) {
    asm("mma.sync.aligned.m16n8k16.row.col.f32.f16.f16.f32 "
        "{%0,%1,%2,%3}, {%4,%5,%6,%7}, {%8,%9}, {%0,%1,%2,%3};"
        : "+f"(c0), "+f"(c1), "+f"(c2), "+f"(c3)
        : "r"(a0), "r"(a1), "r"(a2), "r"(a3), "r"(b0), "r"(b1));
}

// ---------------- B fragment prep: w[o][c*9+k] f32 -> per-lane HMMA frags ----
__global__ void prep_bfrag(const float* __restrict__ w) {
    int i = blockIdx.x * blockDim.x + threadIdx.x;   // (step*32+lane)*8 + nt
    if (i < NSTEPS*32*8) {
        int nt   = i & 7;
        int sl   = i >> 3;
        int lane = sl & 31;
        int step = sl >> 5;
        int o    = nt*8 + (lane >> 2);
        int kb   = step*16 + (lane & 3)*2;
        float v[4];
        #pragma unroll
        for (int q = 0; q < 4; ++q) {
            int k  = kb + (q >> 1)*8 + (q & 1);   // kb, kb+1, kb+8, kb+9
            int c  = k / 9;
            int kk = k - 9*c;
            v[q] = w[(o*Cch + c)*9 + kk];
        }
        uint2 r;
        r.x = packh2(v[0], v[1]);
        r.y = packh2(v[2], v[3]);
        d_bfrag[i] = r;
    }
}

// ---------------- A-pair generation (rows r0, r1) for one global-k ----------
__device__ __forceinline__ float2 gen_pair(const float* __restrict__ bs,
                                           const float* __restrict__ gss,
                                           int cg, int kg, int r0, int r1) {
    unsigned c = __umulhi((unsigned)kg, 0x38E38E39u) >> 1;   // kg/9
    int kk = kg - 9*(int)c;
    int cl = (int)c - cg*16;
    int di = (kk*86) >> 8;                                    // kk/3
    int dj = kk - 3*di;
    const float* xp = bs + cl*XSTR + di*132 + dj;
    const float* gp = bs + XGC_OFF + cl*GCSTR;
    const float* sp = gss + kk*GSSTR;
    float t0 = tanh_fast(gp[r0] + sp[r0]);
    float t1 = tanh_fast(gp[r1] + sp[r1]);
    float x0 = xp[r0], x1 = xp[r1];
    return make_float2(fmaf(x0, t0, x0), fmaf(x1, t1, x1));
}

// ---------------- main kernel ----------------
extern __shared__ float sm[];

__global__ void __launch_bounds__(THREADS, 2)
paka_hmma(const float* __restrict__ x,
          const float* __restrict__ gc,
          const float* __restrict__ gsp,
          float* __restrict__ out)
{
    const int tid  = threadIdx.x;
    const int lane = tid & 31;
    const int wid  = tid >> 5;
    const int t    = blockIdx.x;
    const int b    = t >> 7;
    const int h    = t & 127;

    const uint32_t sbase = smem_u32(sm);

    // ---- stage gs (once) ----
    {
        #pragma unroll
        for (int it = 0; it < 5; ++it) {
            int idx = tid + it*THREADS;
            if (idx < GS_ELEMS) {
                int kk = idx >> 7, w = idx & 127;
                cp4(sbase + (GS_OFF + kk*GSSTR + w)*4,
                    gsp + (((size_t)b*9 + kk)*Hh + h)*Wwi + w, 4);
            }
        }
    }
    // ---- stage chunk 0 ----
    const float* xB  = x  + (size_t)b*Cch*HW;
    const float* gcB = gc + (size_t)b*Cch*HW + (size_t)h*Wwi;
    auto stage_chunk = [&](int cg) {
        const uint32_t dst = sbase + (cg & 1)*BUF_FL*4;
        const float* xc = xB + (size_t)cg*16*HW;
        #pragma unroll
        for (int it = 0; it < 25; ++it) {
            int idx = tid + it*THREADS;
            if (idx < X_ELEMS) {
                int r   = (int)(((unsigned)idx * 31776u) >> 22);   // idx/132
                int col = idx - r*132;
                int cl  = (r*86) >> 8;                             // r/3
                int di  = r - 3*cl;
                int gh  = h - 1 + di;
                int gw  = col - 1;
                bool inb = ((unsigned)gh < Hh) & ((unsigned)gw < Wwi);
                const float* src = inb ? (xc + (size_t)cl*HW + gh*Wwi + gw) : xB;
                cp4(dst + (uint32_t)(cl*XSTR + di*132 + col)*4, src, inb ? 4 : 0);
            }
        }
        const float* gcc = gcB + (size_t)cg*16*HW;
        #pragma unroll
        for (int it = 0; it < 8; ++it) {
            int idx = tid + it*THREADS;
            int cl = idx >> 7, w = idx & 127;
            cp4(dst + (uint32_t)(XGC_OFF + cl*GCSTR + w)*4, gcc + (size_t)cl*HW + w, 4);
        }
    };
    stage_chunk(0);
    cp_commit();

    const int r0 = wid*16 + (lane >> 2);
    const int r1 = r0 + 8;
    const int qp = (lane & 3)*2;

    float acc[32];
    #pragma unroll
    for (int i = 0; i < 32; ++i) acc[i] = 0.f;

    const float* gss = sm + GS_OFF;

    for (int cg = 0; cg < NCHUNK; ++cg) {
        if (cg + 1 < NCHUNK) { stage_chunk(cg + 1); cp_commit(); cp_wait1(); }
        else                 { cp_wait0(); }
        __syncthreads();

        const float* bs = sm + (cg & 1)*BUF_FL;

        #pragma unroll
        for (int s = 0; s < 9; ++s) {
            const int step = cg*9 + s;
            const int k0   = step*16 + qp;

            // B fragments: 4x LDG.128, identical across warps -> L1 hits
            // slot (step,lane) = 8 x uint2 = 64 B = 4 x uint4
            const uint4* bp = reinterpret_cast<const uint4*>(d_bfrag)
                            + ((size_t)step*32 + lane)*4;
            uint4 B0 = bp[0];
            uint4 B1 = bp[1];

            // generate A fragments
            float2 v0 = gen_pair(bs, gss, cg, k0,     r0, r1);
            float2 v1 = gen_pair(bs, gss, cg, k0 + 1, r0, r1);
            float2 v8 = gen_pair(bs, gss, cg, k0 + 8, r0, r1);
            float2 v9 = gen_pair(bs, gss, cg, k0 + 9, r0, r1);
            uint32_t a0 = packh2(v0.x, v1.x);
            uint32_t a1 = packh2(v0.y, v1.y);
            uint32_t a2 = packh2(v8.x, v9.x);
            uint32_t a3 = packh2(v8.y, v9.y);

            hmma(acc[0],  acc[1],  acc[2],  acc[3],  a0,a1,a2,a3, B0.x, B0.y);
            hmma(acc[4],  acc[5],  acc[6],  acc[7],  a0,a1,a2,a3, B0.z, B0.w);
            hmma(acc[8],  acc[9],  acc[10], acc[11], a0,a1,a2,a3, B1.x, B1.y);
            hmma(acc[12], acc[13], acc[14], acc[15], a0,a1,a2,a3, B1.z, B1.w);

            uint4 B2 = bp[2];
            uint4 B3 = bp[3];
            hmma(acc[16], acc[17], acc[18], acc[19], a0,a1,a2,a3, B2.x, B2.y);
            hmma(acc[20], acc[21], acc[22], acc[23], a0,a1,a2,a3, B2.z, B2.w);
            hmma(acc[24], acc[25], acc[26], acc[27], a0,a1,a2,a3, B3.x, B3.y);
            hmma(acc[28], acc[29], acc[30], acc[31], a0,a1,a2,a3, B3.z, B3.w);
        }
        __syncthreads();   // all done reading bs before it is restaged
    }

    // ---- epilogue: D fragments -> out[b][o][h][w] ----
    float* ob = out + ((size_t)b*Och)*HW + (size_t)h*Wwi;
    #pragma unroll
    for (int nt = 0; nt < 8; ++nt) {
        const int o0 = nt*8 + qp;
        float* p = ob + (size_t)o0*HW;
        p[r0]      = acc[nt*4 + 0];
        p[HW + r0] = acc[nt*4 + 1];
        p[r1]      = acc[nt*4 + 2];
        p[HW + r1] = acc[nt*4 + 3];
    }
}

extern "C" void kernel_launch(void* const* d_in, const int* in_sizes, int n_in,
                              void* d_out, int out_size) {
    const float* x  = (const float*)d_in[0];
    const float* gc = (const float*)d_in[1];
    const float* gs = (const float*)d_in[2];
    const float* w  = (const float*)d_in[3];
    float* out = (float*)d_out;

    prep_bfrag<<<(NSTEPS*32*8 + 255)/256, 256>>>(w);

    const int smem_bytes = SMEM_FL * (int)sizeof(float);
    (void)cudaFuncSetAttribute(paka_hmma,
                               cudaFuncAttributeMaxDynamicSharedMemorySize,
                               smem_bytes);
    paka_hmma<<<NTILES, THREADS, smem_bytes>>>(x, gc, gs, out);
}